// round 2
// baseline (speedup 1.0000x reference)
#include <cuda_runtime.h>
#include <math.h>

#define BB 64
#define TT 32
#define EE 300
#define HH 1024

// Persistent state scratch (device globals — no allocation allowed)
__device__ float g_h1[2][BB * HH];
__device__ float g_h2[2][BB * HH];
__device__ float g_c1[BB * HH];
__device__ float g_c2[BB * HH];

__global__ void init_states_kernel() {
    int i = blockIdx.x * blockDim.x + threadIdx.x;
    if (i < BB * HH) {
        g_h1[0][i] = 0.f;
        g_h2[0][i] = 0.f;
        g_c1[i] = 0.f;
        g_c2[i] = 0.f;
    }
}

// Fused GEMM + LSTM cell for one layer, one timestep.
// Block: 128 threads, handles all 64 batch rows x 8 hidden units (32 gate cols).
// grid.x = H/8 = 128 blocks.
// Gate col c in [0,32): gate q = c>>3, unit u = c&7, weight row r = q*H + u0 + u.
__global__ __launch_bounds__(128) void lstm_step_kernel(
    const float* __restrict__ Wih,   // [4H, Kx] row-major
    const float* __restrict__ Whh,   // [4H, H]
    const float* __restrict__ bih,   // [4H]
    const float* __restrict__ bhh,   // [4H]
    const int*   __restrict__ questions, // [B, T] (layer1 only)
    const int*   __restrict__ qlen,      // [B]
    const float* __restrict__ embed,     // [V, E] (layer1) or nullptr
    const float* __restrict__ xin,       // [B, H] (layer2 input) or nullptr
    const float* __restrict__ hprev,     // [B, H] this layer's previous h
    float*       __restrict__ cbuf,      // [B, H] c state (in/out, same buffer)
    float*       __restrict__ hout,      // [B, H] new h (ping-pong target)
    int t, int Kx)
{
    __shared__ float actS[BB][36];
    __shared__ float wS[32][36];
    __shared__ float gsm[BB][33];
    __shared__ int   qidxS[BB];

    const int tid = threadIdx.x;
    const int u0  = blockIdx.x * 8;

    if (embed != nullptr && tid < BB) {
        qidxS[tid] = questions[tid * TT + t];
    }

    float acc[4][4];
#pragma unroll
    for (int ri = 0; ri < 4; ++ri)
#pragma unroll
        for (int ci = 0; ci < 4; ++ci) acc[ri][ci] = 0.f;

    const int rb = (tid >> 3) * 4;  // batch-row base (0..60)
    const int cb = (tid & 7) * 4;   // gate-col base (0..28)

    for (int ph = 0; ph < 2; ++ph) {
        const int K = ph ? HH : Kx;
        const float* __restrict__ W = ph ? Whh : Wih;
        const int ntile = (K + 31) >> 5;
        for (int tle = 0; tle < ntile; ++tle) {
            const int k0 = tle << 5;
            __syncthreads();  // protects qidxS (first iter) and tile reuse
            // load activation tile [64 x 32]
            for (int i = tid; i < BB * 32; i += 128) {
                int b = i >> 5, k = i & 31, gk = k0 + k;
                float v = 0.f;
                if (gk < K) {
                    if (ph)              v = hprev[b * HH + gk];
                    else if (embed)      v = embed[qidxS[b] * EE + gk];
                    else                 v = xin[b * HH + gk];
                }
                actS[b][k] = v;
            }
            // load weight tile [32 x 32]
            for (int i = tid; i < 32 * 32; i += 128) {
                int c = i >> 5, k = i & 31, gk = k0 + k;
                int r = ((c >> 3) << 10) + u0 + (c & 7);
                wS[c][k] = (gk < K) ? W[r * K + gk] : 0.f;
            }
            __syncthreads();
#pragma unroll
            for (int kq = 0; kq < 8; ++kq) {
                float4 a[4], w[4];
#pragma unroll
                for (int ri = 0; ri < 4; ++ri)
                    a[ri] = *(const float4*)&actS[rb + ri][kq * 4];
#pragma unroll
                for (int ci = 0; ci < 4; ++ci)
                    w[ci] = *(const float4*)&wS[cb + ci][kq * 4];
#pragma unroll
                for (int ri = 0; ri < 4; ++ri)
#pragma unroll
                    for (int ci = 0; ci < 4; ++ci) {
                        acc[ri][ci] += a[ri].x * w[ci].x;
                        acc[ri][ci] += a[ri].y * w[ci].y;
                        acc[ri][ci] += a[ri].z * w[ci].z;
                        acc[ri][ci] += a[ri].w * w[ci].w;
                    }
            }
        }
    }

    __syncthreads();
#pragma unroll
    for (int ri = 0; ri < 4; ++ri)
#pragma unroll
        for (int ci = 0; ci < 4; ++ci)
            gsm[rb + ri][cb + ci] = acc[ri][ci];
    __syncthreads();

    // Epilogue: LSTM cell for 64 batch x 8 units = 512 pairs
    for (int p = tid; p < BB * 8; p += 128) {
        int b = p >> 3, u = p & 7;
        int gu = u0 + u;
        float gi = gsm[b][u]      + bih[gu]          + bhh[gu];
        float gf = gsm[b][u + 8]  + bih[gu + HH]     + bhh[gu + HH];
        float gg = gsm[b][u + 16] + bih[gu + 2*HH]   + bhh[gu + 2*HH];
        float go = gsm[b][u + 24] + bih[gu + 3*HH]   + bhh[gu + 3*HH];
        float c_old = cbuf[b * HH + gu];
        float h_old = hprev[b * HH + gu];
        float si = 1.f / (1.f + expf(-gi));
        float sf = 1.f / (1.f + expf(-gf));
        float so = 1.f / (1.f + expf(-go));
        float tg = tanhf(gg);
        float cn = sf * c_old + si * tg;
        float hn = so * tanhf(cn);
        bool active = (t < qlen[b]);
        cbuf[b * HH + gu] = active ? cn : c_old;
        hout[b * HH + gu] = active ? hn : h_old;
    }
}

// Output: E_q [B,1024,28,28] = tiled h2, then h1, h2, c1, c2 each [B,1,H].
__global__ void write_output_kernel(
    float* __restrict__ out,
    const float* __restrict__ h1,
    const float* __restrict__ h2,
    const float* __restrict__ c1,
    const float* __restrict__ c2)
{
    const unsigned n0q = (unsigned)BB * HH * 784u / 4u;  // 12,845,056 float4s
    const unsigned sq  = (unsigned)BB * HH / 4u;         // 16,384 float4s per state
    unsigned idx = blockIdx.x * blockDim.x + threadIdx.x;
    unsigned totq = n0q + 4u * sq;
    if (idx >= totq) return;
    float4* out4 = (float4*)out;
    if (idx < n0q) {
        unsigned bh = idx / 196u;  // b*1024 + hidden index (784/4 = 196)
        float v = h2[bh];
        out4[idx] = make_float4(v, v, v, v);
    } else {
        unsigned r = idx - n0q;
        unsigned sec = r / sq;
        unsigned off = r % sq;
        const float* src = (sec == 0) ? h1 : (sec == 1) ? h2 : (sec == 2) ? c1 : c2;
        out4[idx] = ((const float4*)src)[off];
    }
}

extern "C" void kernel_launch(void* const* d_in, const int* in_sizes, int n_in,
                              void* d_out, int out_size) {
    const int*   questions = (const int*)d_in[0];
    const int*   qlen      = (const int*)d_in[1];
    const float* embed     = (const float*)d_in[2];
    const float* Wih1      = (const float*)d_in[3];
    const float* Whh1      = (const float*)d_in[4];
    const float* bih1      = (const float*)d_in[5];
    const float* bhh1      = (const float*)d_in[6];
    const float* Wih2      = (const float*)d_in[7];
    const float* Whh2      = (const float*)d_in[8];
    const float* bih2      = (const float*)d_in[9];
    const float* bhh2      = (const float*)d_in[10];

    void* p;
    cudaGetSymbolAddress(&p, g_h1); float (*h1b)[BB*HH] = (float(*)[BB*HH])p;
    cudaGetSymbolAddress(&p, g_h2); float (*h2b)[BB*HH] = (float(*)[BB*HH])p;
    cudaGetSymbolAddress(&p, g_c1); float* c1p = (float*)p;
    cudaGetSymbolAddress(&p, g_c2); float* c2p = (float*)p;

    init_states_kernel<<<(BB * HH + 255) / 256, 256>>>();

    for (int t = 0; t < TT; ++t) {
        float* h1r = h1b[t & 1];
        float* h1w = h1b[(t + 1) & 1];
        float* h2r = h2b[t & 1];
        float* h2w = h2b[(t + 1) & 1];
        // Layer 1: x from embedding gather, K = 300 + 1024
        lstm_step_kernel<<<HH / 8, 128>>>(
            Wih1, Whh1, bih1, bhh1, questions, qlen, embed, nullptr,
            h1r, c1p, h1w, t, EE);
        // Layer 2: x = new h1, K = 1024 + 1024
        lstm_step_kernel<<<HH / 8, 128>>>(
            Wih2, Whh2, bih2, bhh2, questions, qlen, nullptr, h1w,
            h2r, c2p, h2w, t, HH);
    }

    // final states live in buffer index (T % 2) == 0
    unsigned totq = (unsigned)BB * HH * 784u / 4u + (unsigned)BB * HH;
    write_output_kernel<<<(totq + 255) / 256, 256>>>(
        (float*)d_out, h1b[0], h2b[0], c1p, c2p);
}

// round 4
// speedup vs baseline: 6.6720x; 6.6720x over previous
#include <cuda_runtime.h>
#include <math.h>

#define BB 64
#define TT 32
#define EE 300
#define HH 1024

// Persistent state scratch (device globals — no allocation allowed)
__device__ float g_h1[2][BB * HH];
__device__ float g_h2[2][BB * HH];
__device__ float g_c1[BB * HH];
__device__ float g_c2[BB * HH];

__global__ void init_states_kernel() {
    int i = blockIdx.x * blockDim.x + threadIdx.x;
    if (i < BB * HH) {
        g_h1[0][i] = 0.f;
        g_h2[0][i] = 0.f;
        g_c1[i] = 0.f;
        g_c2[i] = 0.f;
    }
}

__device__ __forceinline__ unsigned cvt_tf32(float x) {
    unsigned r;
    asm("cvt.rna.tf32.f32 %0, %1;" : "=r"(r) : "f"(x));
    return r;
}

__device__ __forceinline__ void cp16(unsigned dst, const void* src, int valid) {
    asm volatile("cp.async.cg.shared.global [%0], [%1], 16, %2;"
                 :: "r"(dst), "l"(src), "r"(valid ? 16 : 0));
}

// Fused tf32-MMA GEMM + LSTM cell for one layer, one timestep.
// Block: 128 threads (4 warps). Block output tile: M=64 (batch) x N=32 gate-cols,
// where col c: gate q = c>>3 (i/f/g/o), unit = u0 + (c&7). grid.x = 128.
// Warp w: rows [16w,16w+16). Each warp's 4 mma n-subtiles (8 cols each) are
// exactly the 4 gates of the same 8 units -> LSTM cell epilogue is thread-local.
__global__ __launch_bounds__(128) void lstm_step_mma(
    const float* __restrict__ Wih,   // [4H, Kx] row-major
    const float* __restrict__ Whh,   // [4H, H]
    const float* __restrict__ bih,   // [4H]
    const float* __restrict__ bhh,   // [4H]
    const int*   __restrict__ questions, // [B, T] (layer1 only)
    const int*   __restrict__ qlen,      // [B]
    const float* __restrict__ embed,     // [V, E] (layer1) or nullptr
    const float* __restrict__ xin,       // [B, H] (layer2 input) or nullptr
    const float* __restrict__ hprev,     // [B, H] this layer's previous h
    float*       __restrict__ cbuf,      // [B, H] c state (in/out)
    float*       __restrict__ hout,     // [B, H] new h (ping-pong target)
    int t, int Kx)
{
    __shared__ __align__(16) float As[2][64 * 32];  // A tile, swizzled [m][k]
    __shared__ __align__(16) float Ws[2][32 * 32];  // W tile, swizzled [n][k]
    __shared__ int qidxS[BB];

    const int tid  = threadIdx.x;
    const int lane = tid & 31;
    const int warp = tid >> 5;
    const int u0   = blockIdx.x * 8;

    if (embed != nullptr && tid < BB) qidxS[tid] = questions[tid * TT + t];
    __syncthreads();

    const int ntile0 = (Kx + 31) >> 5;      // input-phase K tiles
    const int NT = ntile0 + (HH >> 5);      // + recurrent-phase tiles

    unsigned asb0 = (unsigned)__cvta_generic_to_shared(&As[0][0]);
    unsigned asb1 = (unsigned)__cvta_generic_to_shared(&As[1][0]);
    unsigned wsb0 = (unsigned)__cvta_generic_to_shared(&Ws[0][0]);
    unsigned wsb1 = (unsigned)__cvta_generic_to_shared(&Ws[1][0]);

    float acc[4][4];
#pragma unroll
    for (int j = 0; j < 4; ++j)
#pragma unroll
        for (int r = 0; r < 4; ++r) acc[j][r] = 0.f;

    // ---- tile issue (cp.async, zfill past K) ----
    auto issue_tile = [&](int tt, int stage) {
        const int phase = (tt >= ntile0);
        const int k0 = phase ? ((tt - ntile0) << 5) : (tt << 5);
        const int K  = phase ? HH : Kx;
        const float* __restrict__ Wp = phase ? Whh : Wih;
        const unsigned ab = stage ? asb1 : asb0;
        const unsigned wb = stage ? wsb1 : wsb0;
        // A tile: 64 rows x 8 float4s = 512 float4s, 4 per thread
#pragma unroll
        for (int j = 0; j < 4; ++j) {
            int idx = tid + j * 128;
            int m = idx >> 3, k4 = idx & 7;
            int kk = k0 + (k4 << 2);
            int valid = kk < K;
            int ks = valid ? kk : 0;
            const float* src;
            if (phase)            src = hprev + m * HH + ks;
            else if (embed)       src = embed + (size_t)qidxS[m] * EE + ks;
            else                  src = xin + m * HH + ks;
            unsigned dst = ab + (unsigned)((m * 8 + (k4 ^ (m & 7))) * 16);
            cp16(dst, src, valid);
        }
        // W tile: 32 rows x 8 float4s = 256 float4s, 2 per thread
#pragma unroll
        for (int j = 0; j < 2; ++j) {
            int idx = tid + j * 128;
            int n = idx >> 3, k4 = idx & 7;
            int kk = k0 + (k4 << 2);
            int valid = kk < K;
            int r = ((n >> 3) << 10) + u0 + (n & 7);     // gate*H + unit
            const float* src = Wp + (size_t)r * K + (valid ? kk : 0);
            unsigned dst = wb + (unsigned)((n * 8 + (k4 ^ (n & 7))) * 16);
            cp16(dst, src, valid);
        }
        asm volatile("cp.async.commit_group;");
    };

    issue_tile(0, 0);

    const int g  = lane >> 2;   // 0..7
    const int th = lane & 3;    // 0..3
    const int mrow = warp * 16 + g;

    for (int tt = 0; tt < NT; ++tt) {
        if (tt + 1 < NT) {
            issue_tile(tt + 1, (tt + 1) & 1);
            asm volatile("cp.async.wait_group 1;");
        } else {
            asm volatile("cp.async.wait_group 0;");
        }
        __syncthreads();

        const float* __restrict__ A = As[tt & 1];
        const float* __restrict__ W = Ws[tt & 1];

#pragma unroll
        for (int c = 0; c < 4; ++c) {          // k-chunk of 8: kc = 8c
            const int xr0 = ((2 * c)     ^ g) << 2;   // swizzled k4 offset (both +0/+8 rows: low3 bits of m == g)
            const int xr1 = ((2 * c + 1) ^ g) << 2;
            unsigned a0 = cvt_tf32(A[ mrow      * 32 + xr0 + th]);
            unsigned a1 = cvt_tf32(A[(mrow + 8) * 32 + xr0 + th]);
            unsigned a2 = cvt_tf32(A[ mrow      * 32 + xr1 + th]);
            unsigned a3 = cvt_tf32(A[(mrow + 8) * 32 + xr1 + th]);
#pragma unroll
            for (int j = 0; j < 4; ++j) {      // n-subtile == gate j
                const int n = j * 8 + g;
                unsigned b0 = cvt_tf32(W[n * 32 + xr0 + th]);
                unsigned b1 = cvt_tf32(W[n * 32 + xr1 + th]);
                asm volatile(
                    "mma.sync.aligned.m16n8k8.row.col.f32.tf32.tf32.f32 "
                    "{%0,%1,%2,%3}, {%4,%5,%6,%7}, {%8,%9}, {%0,%1,%2,%3};"
                    : "+f"(acc[j][0]), "+f"(acc[j][1]),
                      "+f"(acc[j][2]), "+f"(acc[j][3])
                    : "r"(a0), "r"(a1), "r"(a2), "r"(a3), "r"(b0), "r"(b1));
            }
        }
        __syncthreads();
    }

    // ---- thread-local LSTM cell epilogue ----
    // acc[j][r]: gate j at (row = warp*16 + g + 8*(r>>1), unit = u0 + 2*th + (r&1))
#pragma unroll
    for (int r = 0; r < 4; ++r) {
        int b  = warp * 16 + g + ((r >> 1) << 3);
        int gu = u0 + 2 * th + (r & 1);
        float gi = acc[0][r] + bih[gu]          + bhh[gu];
        float gf = acc[1][r] + bih[gu + HH]     + bhh[gu + HH];
        float gg = acc[2][r] + bih[gu + 2*HH]   + bhh[gu + 2*HH];
        float go = acc[3][r] + bih[gu + 3*HH]   + bhh[gu + 3*HH];
        float c_old = cbuf[b * HH + gu];
        float h_old = hprev[b * HH + gu];
        float si = 1.f / (1.f + expf(-gi));
        float sf = 1.f / (1.f + expf(-gf));
        float so = 1.f / (1.f + expf(-go));
        float tg = tanhf(gg);
        float cn = sf * c_old + si * tg;
        float hn = so * tanhf(cn);
        bool active = (t < qlen[b]);
        cbuf[b * HH + gu] = active ? cn : c_old;
        hout[b * HH + gu] = active ? hn : h_old;
    }
}

// Output: E_q [B,1024,28,28] = tiled h2, then h1, h2, c1, c2 each [B,1,H].
__global__ void write_output_kernel(
    float* __restrict__ out,
    const float* __restrict__ h1,
    const float* __restrict__ h2,
    const float* __restrict__ c1,
    const float* __restrict__ c2)
{
    const unsigned n0q = (unsigned)BB * HH * 784u / 4u;  // float4 count of E_q
    const unsigned sq  = (unsigned)BB * HH / 4u;
    unsigned idx = blockIdx.x * blockDim.x + threadIdx.x;
    unsigned totq = n0q + 4u * sq;
    if (idx >= totq) return;
    float4* out4 = (float4*)out;
    if (idx < n0q) {
        unsigned bh = idx / 196u;   // 784/4 float4s per (b, hidden)
        float v = h2[bh];
        out4[idx] = make_float4(v, v, v, v);
    } else {
        unsigned r = idx - n0q;
        unsigned sec = r / sq;
        unsigned off = r % sq;
        const float* src = (sec == 0) ? h1 : (sec == 1) ? h2 : (sec == 2) ? c1 : c2;
        out4[idx] = ((const float4*)src)[off];
    }
}

extern "C" void kernel_launch(void* const* d_in, const int* in_sizes, int n_in,
                              void* d_out, int out_size) {
    const int*   questions = (const int*)d_in[0];
    const int*   qlen      = (const int*)d_in[1];
    const float* embed     = (const float*)d_in[2];
    const float* Wih1      = (const float*)d_in[3];
    const float* Whh1      = (const float*)d_in[4];
    const float* bih1      = (const float*)d_in[5];
    const float* bhh1      = (const float*)d_in[6];
    const float* Wih2      = (const float*)d_in[7];
    const float* Whh2      = (const float*)d_in[8];
    const float* bih2      = (const float*)d_in[9];
    const float* bhh2      = (const float*)d_in[10];

    void* p;
    cudaGetSymbolAddress(&p, g_h1); float (*h1b)[BB*HH] = (float(*)[BB*HH])p;
    cudaGetSymbolAddress(&p, g_h2); float (*h2b)[BB*HH] = (float(*)[BB*HH])p;
    cudaGetSymbolAddress(&p, g_c1); float* c1p = (float*)p;
    cudaGetSymbolAddress(&p, g_c2); float* c2p = (float*)p;

    init_states_kernel<<<(BB * HH + 255) / 256, 256>>>();

    for (int t = 0; t < TT; ++t) {
        float* h1r = h1b[t & 1];
        float* h1w = h1b[(t + 1) & 1];
        float* h2r = h2b[t & 1];
        float* h2w = h2b[(t + 1) & 1];
        // Layer 1: x from embedding gather, K = 300 + 1024
        lstm_step_mma<<<HH / 8, 128>>>(
            Wih1, Whh1, bih1, bhh1, questions, qlen, embed, nullptr,
            h1r, c1p, h1w, t, EE);
        // Layer 2: x = new h1, K = 1024 + 1024
        lstm_step_mma<<<HH / 8, 128>>>(
            Wih2, Whh2, bih2, bhh2, questions, qlen, nullptr, h1w,
            h2r, c2p, h2w, t, HH);
    }

    // final states live in buffer index (T % 2) == 0
    unsigned totq = (unsigned)BB * HH * 784u / 4u + (unsigned)BB * HH;
    write_output_kernel<<<(totq + 255) / 256, 256>>>(
        (float*)d_out, h1b[0], h2b[0], c1p, c2p);
}

// round 6
// speedup vs baseline: 8.0280x; 1.2032x over previous
#include <cuda_runtime.h>
#include <math.h>

#define BB 64
#define TT 32
#define EE 300
#define HH 1024

#define NSTAGE 8
#define A_TILE_BYTES (64 * 32 * 4)                 // 8192
#define W_TILE_BYTES (32 * 32 * 4)                 // 4096
#define STAGE_BYTES  (A_TILE_BYTES + W_TILE_BYTES) // 12288
#define SMEM_DYN     (NSTAGE * STAGE_BYTES)        // 98304

// Persistent state scratch (device globals — no allocation allowed)
__device__ float g_h1[2][BB * HH];
__device__ float g_h2[2][BB * HH];
__device__ float g_c1[BB * HH];
__device__ float g_c2[BB * HH];

__global__ void init_states_kernel() {
    int i = blockIdx.x * blockDim.x + threadIdx.x;
    if (i < BB * HH) {
        g_h1[0][i] = 0.f;
        g_h2[0][i] = 0.f;
        g_c1[i] = 0.f;
        g_c2[i] = 0.f;
    }
}

__device__ __forceinline__ unsigned cvt_tf32(float x) {
    unsigned r;
    asm("cvt.rna.tf32.f32 %0, %1;" : "=r"(r) : "f"(x));
    return r;
}

__device__ __forceinline__ void cp16(unsigned dst, const void* src, int valid) {
    asm volatile("cp.async.cg.shared.global [%0], [%1], 16, %2;"
                 :: "r"(dst), "l"(src), "r"(valid ? 16 : 0));
}

// Fused tf32-MMA GEMM + LSTM cell for one layer, one timestep.
// Block: 128 threads (4 warps). Block tile: M=64 (batch) x N=32 gate-cols,
// col c: gate q = c>>3 (i/f/g/o), unit = u0 + (c&7). grid.x = 128.
// 8-stage cp.async ring hides DRAM/L2 latency; one __syncthreads per k-tile.
__global__ __launch_bounds__(128) void lstm_step_mma(
    const float* __restrict__ Wih,   // [4H, Kx] row-major
    const float* __restrict__ Whh,   // [4H, H]
    const float* __restrict__ bih,   // [4H]
    const float* __restrict__ bhh,   // [4H]
    const int*   __restrict__ questions, // [B, T] (layer1 only)
    const int*   __restrict__ qlen,      // [B]
    const float* __restrict__ embed,     // [V, E] (layer1) or nullptr
    const float* __restrict__ xin,       // [B, H] (layer2 input) or nullptr
    const float* __restrict__ hprev,     // [B, H] this layer's previous h
    float*       __restrict__ cbuf,      // [B, H] c state (in/out)
    float*       __restrict__ hout,      // [B, H] new h (ping-pong target)
    int t, int Kx)
{
    extern __shared__ __align__(16) float smem_dyn[];
    __shared__ int qidxS[BB];

    const int tid  = threadIdx.x;
    const int lane = tid & 31;
    const int warp = tid >> 5;
    const int u0   = blockIdx.x * 8;

    if (embed != nullptr && tid < BB) qidxS[tid] = questions[tid * TT + t];
    __syncthreads();

    const int ntile0 = (Kx + 31) >> 5;      // input-phase K tiles
    const int NT = ntile0 + (HH >> 5);      // + recurrent-phase tiles

    const unsigned smem_base = (unsigned)__cvta_generic_to_shared(smem_dyn);

    float acc[4][4];
#pragma unroll
    for (int j = 0; j < 4; ++j)
#pragma unroll
        for (int r = 0; r < 4; ++r) acc[j][r] = 0.f;

    // ---- tile issue (cp.async, zfill past K) ----
    auto issue_tile = [&](int tt, int stage) {
        const int phase = (tt >= ntile0);
        const int k0 = phase ? ((tt - ntile0) << 5) : (tt << 5);
        const int K  = phase ? HH : Kx;
        const float* __restrict__ Wp = phase ? Whh : Wih;
        const unsigned ab = smem_base + (unsigned)(stage * STAGE_BYTES);
        const unsigned wb = ab + A_TILE_BYTES;
        // A tile: 64 rows x 8 float4s = 512 float4s, 4 per thread
#pragma unroll
        for (int j = 0; j < 4; ++j) {
            int idx = tid + j * 128;
            int m = idx >> 3, k4 = idx & 7;
            int kk = k0 + (k4 << 2);
            int valid = kk < K;
            int ks = valid ? kk : 0;
            const float* src;
            if (phase)            src = hprev + m * HH + ks;
            else if (embed)       src = embed + (size_t)qidxS[m] * EE + ks;
            else                  src = xin + m * HH + ks;
            unsigned dst = ab + (unsigned)((m * 8 + (k4 ^ (m & 7))) * 16);
            cp16(dst, src, valid);
        }
        // W tile: 32 rows x 8 float4s = 256 float4s, 2 per thread
#pragma unroll
        for (int j = 0; j < 2; ++j) {
            int idx = tid + j * 128;
            int n = idx >> 3, k4 = idx & 7;
            int kk = k0 + (k4 << 2);
            int valid = kk < K;
            int r = ((n >> 3) << 10) + u0 + (n & 7);     // gate*H + unit
            const float* src = Wp + (size_t)r * K + (valid ? kk : 0);
            unsigned dst = wb + (unsigned)((n * 8 + (k4 ^ (n & 7))) * 16);
            cp16(dst, src, valid);
        }
    };

    // Prologue: fill NSTAGE-1 stages (NT >= 42 always, so no bounds guards)
#pragma unroll
    for (int p = 0; p < NSTAGE - 1; ++p) {
        issue_tile(p, p);
        asm volatile("cp.async.commit_group;");
    }

    const int g  = lane >> 2;   // 0..7
    const int th = lane & 3;    // 0..3
    const int mrow = warp * 16 + g;

    for (int tt = 0; tt < NT; ++tt) {
        asm volatile("cp.async.wait_group %0;" :: "n"(NSTAGE - 2));
        __syncthreads();

        const int stage = tt & (NSTAGE - 1);
        const float* __restrict__ A = smem_dyn + stage * (STAGE_BYTES / 4);
        const float* __restrict__ W = A + (A_TILE_BYTES / 4);

#pragma unroll
        for (int c = 0; c < 4; ++c) {          // k-chunk of 8: kc = 8c
            const int xr0 = ((2 * c)     ^ g) << 2;   // swizzled k4 offset (rows m, m+8 share low3 bits == g)
            const int xr1 = ((2 * c + 1) ^ g) << 2;
            unsigned a0 = cvt_tf32(A[ mrow      * 32 + xr0 + th]);
            unsigned a1 = cvt_tf32(A[(mrow + 8) * 32 + xr0 + th]);
            unsigned a2 = cvt_tf32(A[ mrow      * 32 + xr1 + th]);
            unsigned a3 = cvt_tf32(A[(mrow + 8) * 32 + xr1 + th]);
#pragma unroll
            for (int j = 0; j < 4; ++j) {      // n-subtile == gate j
                const int n = j * 8 + g;
                unsigned b0 = cvt_tf32(W[n * 32 + xr0 + th]);
                unsigned b1 = cvt_tf32(W[n * 32 + xr1 + th]);
                asm volatile(
                    "mma.sync.aligned.m16n8k8.row.col.f32.tf32.tf32.f32 "
                    "{%0,%1,%2,%3}, {%4,%5,%6,%7}, {%8,%9}, {%0,%1,%2,%3};"
                    : "+f"(acc[j][0]), "+f"(acc[j][1]),
                      "+f"(acc[j][2]), "+f"(acc[j][3])
                    : "r"(a0), "r"(a1), "r"(a2), "r"(a3), "r"(b0), "r"(b1));
            }
        }

        // Issue next tile into the stage freed at iteration tt-1
        // (ordered against its compute by this iteration's __syncthreads)
        int nt = tt + NSTAGE - 1;
        if (nt < NT) issue_tile(nt, nt & (NSTAGE - 1));
        asm volatile("cp.async.commit_group;");
    }

    // ---- thread-local LSTM cell epilogue ----
    // acc[j][r]: gate j at (row = warp*16 + g + 8*(r>>1), unit = u0 + 2*th + (r&1))
#pragma unroll
    for (int r = 0; r < 4; ++r) {
        int b  = warp * 16 + g + ((r >> 1) << 3);
        int gu = u0 + 2 * th + (r & 1);
        float gi = acc[0][r] + bih[gu]          + bhh[gu];
        float gf = acc[1][r] + bih[gu + HH]     + bhh[gu + HH];
        float gg = acc[2][r] + bih[gu + 2*HH]   + bhh[gu + 2*HH];
        float go = acc[3][r] + bih[gu + 3*HH]   + bhh[gu + 3*HH];
        float c_old = cbuf[b * HH + gu];
        float h_old = hprev[b * HH + gu];
        float si = 1.f / (1.f + expf(-gi));
        float sf = 1.f / (1.f + expf(-gf));
        float so = 1.f / (1.f + expf(-go));
        float tg = tanhf(gg);
        float cn = sf * c_old + si * tg;
        float hn = so * tanhf(cn);
        bool active = (t < qlen[b]);
        cbuf[b * HH + gu] = active ? cn : c_old;
        hout[b * HH + gu] = active ? hn : h_old;
    }
}

// Output: E_q [B,1024,28,28] = tiled h2, then h1, h2, c1, c2 each [B,1,H].
__global__ void write_output_kernel(
    float* __restrict__ out,
    const float* __restrict__ h1,
    const float* __restrict__ h2,
    const float* __restrict__ c1,
    const float* __restrict__ c2)
{
    const unsigned n0q = (unsigned)BB * HH * 784u / 4u;  // float4 count of E_q
    const unsigned sq  = (unsigned)BB * HH / 4u;
    unsigned idx = blockIdx.x * blockDim.x + threadIdx.x;
    unsigned totq = n0q + 4u * sq;
    if (idx >= totq) return;
    float4* out4 = (float4*)out;
    if (idx < n0q) {
        unsigned bh = idx / 196u;   // 784/4 float4s per (b, hidden)
        float v = h2[bh];
        out4[idx] = make_float4(v, v, v, v);
    } else {
        unsigned r = idx - n0q;
        unsigned sec = r / sq;
        unsigned off = r % sq;
        const float* src = (sec == 0) ? h1 : (sec == 1) ? h2 : (sec == 2) ? c1 : c2;
        out4[idx] = ((const float4*)src)[off];
    }
}

extern "C" void kernel_launch(void* const* d_in, const int* in_sizes, int n_in,
                              void* d_out, int out_size) {
    const int*   questions = (const int*)d_in[0];
    const int*   qlen      = (const int*)d_in[1];
    const float* embed     = (const float*)d_in[2];
    const float* Wih1      = (const float*)d_in[3];
    const float* Whh1      = (const float*)d_in[4];
    const float* bih1      = (const float*)d_in[5];
    const float* bhh1      = (const float*)d_in[6];
    const float* Wih2      = (const float*)d_in[7];
    const float* Whh2      = (const float*)d_in[8];
    const float* bih2      = (const float*)d_in[9];
    const float* bhh2      = (const float*)d_in[10];

    void* p;
    cudaGetSymbolAddress(&p, g_h1); float (*h1b)[BB*HH] = (float(*)[BB*HH])p;
    cudaGetSymbolAddress(&p, g_h2); float (*h2b)[BB*HH] = (float(*)[BB*HH])p;
    cudaGetSymbolAddress(&p, g_c1); float* c1p = (float*)p;
    cudaGetSymbolAddress(&p, g_c2); float* c2p = (float*)p;

    cudaFuncSetAttribute(lstm_step_mma,
                         cudaFuncAttributeMaxDynamicSharedMemorySize, SMEM_DYN);

    init_states_kernel<<<(BB * HH + 255) / 256, 256>>>();

    for (int t = 0; t < TT; ++t) {
        float* h1r = h1b[t & 1];
        float* h1w = h1b[(t + 1) & 1];
        float* h2r = h2b[t & 1];
        float* h2w = h2b[(t + 1) & 1];
        // Layer 1: x from embedding gather, K = 300 + 1024
        lstm_step_mma<<<HH / 8, 128, SMEM_DYN>>>(
            Wih1, Whh1, bih1, bhh1, questions, qlen, embed, nullptr,
            h1r, c1p, h1w, t, EE);
        // Layer 2: x = new h1, K = 1024 + 1024
        lstm_step_mma<<<HH / 8, 128, SMEM_DYN>>>(
            Wih2, Whh2, bih2, bhh2, questions, qlen, nullptr, h1w,
            h2r, c2p, h2w, t, HH);
    }

    // final states live in buffer index (T % 2) == 0
    unsigned totq = (unsigned)BB * HH * 784u / 4u + (unsigned)BB * HH;
    write_output_kernel<<<(totq + 255) / 256, 256>>>(
        (float*)d_out, h1b[0], h2b[0], c1p, c2p);
}